// round 14
// baseline (speedup 1.0000x reference)
#include <cuda_runtime.h>
#include <math.h>
#include <stdint.h>

#define BB 16
#define SS 4096
#define HH 768
#define EE 8
#define CHUNKS 32
#define ROWS_PER_BLK 128
#define TS 8
#define NTILES 16
#define NEB 4

// smem layout in floats (total ~31KB -> 3 CTAs/SM)
#define WLO_OFF   0        // [768][4] = 3072  (e0..e3)
#define WHI_OFF   3072     // [768][4] = 3072  (e4..e7)
#define ASH_OFF   6144     // [8][128] = 1024
#define EXPPK_OFF 7168     // NEB x 64 u64 = 512 floats (8B aligned)
#define BIAS_OFF  7680     // [8]
#define DENP_OFF  7688     // [64]
#define MBAR_OFF  7752     // 8 barriers x 8B = 16 floats (8B aligned)
#define SMEM_FLOATS 7768   // 31072 bytes

__device__ float g_num[(size_t)BB * CHUNKS * EE * HH];   // 12.6 MB
__device__ float g_den[BB * CHUNKS * EE];
__device__ float g_attn_scratch[(size_t)BB * EE * SS];

typedef unsigned long long u64;

__device__ __forceinline__ u64 pack2(float lo, float hi) {
    u64 r; asm("mov.b64 %0, {%1, %2};" : "=l"(r) : "f"(lo), "f"(hi)); return r;
}
__device__ __forceinline__ void unpack2(u64 v, float& lo, float& hi) {
    asm("mov.b64 {%0, %1}, %2;" : "=f"(lo), "=f"(hi) : "l"(v));
}
__device__ __forceinline__ void ffma2(u64& d, u64 a, u64 b) {
    asm("fma.rn.f32x2 %0, %1, %2, %3;" : "=l"(d) : "l"(a), "l"(b), "l"(d));
}
__device__ __forceinline__ u64 ldg_cg_u64(const u64* p) {
    u64 v; asm("ld.global.cg.u64 %0, [%1];" : "=l"(v) : "l"(p)); return v;
}
__device__ __forceinline__ void mbar_init(uint32_t mbar, uint32_t cnt) {
    asm volatile("mbarrier.init.shared.b64 [%0], %1;" :: "r"(mbar), "r"(cnt) : "memory");
}
__device__ __forceinline__ void mbar_arrive(uint32_t mbar) {
    asm volatile("mbarrier.arrive.shared.b64 _, [%0];" :: "r"(mbar) : "memory");
}
__device__ __forceinline__ void mbar_wait(uint32_t mbar, uint32_t parity) {
    asm volatile(
        "{\n\t.reg .pred P1;\n\t"
        "WAIT_%=:\n\t"
        "mbarrier.try_wait.parity.acquire.cta.shared::cta.b64 P1, [%0], %1, 0x989680;\n\t"
        "@P1 bra.uni DONE_%=;\n\t"
        "bra.uni WAIT_%=;\n\t"
        "DONE_%=:\n\t}"
        :: "r"(mbar), "r"(parity) : "memory");
}
__device__ __forceinline__ uint32_t smem_u32(const void* p) {
    uint32_t a;
    asm("{ .reg .u64 t; cvta.to.shared.u64 t, %1; cvt.u32.u64 %0, t; }" : "=r"(a) : "l"(p));
    return a;
}

template <int HALF>
__device__ __forceinline__ void red_round(float* v, int lane) {
    bool hi = (lane & HALF) != 0;
#pragma unroll
    for (int m = 0; m < HALF; m++) {
        float mine  = hi ? v[m + HALF] : v[m];
        float yours = hi ? v[m]        : v[m + HALF];
        v[m] = mine + __shfl_xor_sync(0xffffffffu, yours, HALF);
    }
}

__global__ __launch_bounds__(256, 3)
void fused_attn_pass1(const float* __restrict__ x,
                      const float* __restrict__ W,
                      const float* __restrict__ bias,
                      float* __restrict__ attn_out)
{
    extern __shared__ float sm[];
    float* wlo     = sm + WLO_OFF;
    float* whi     = sm + WHI_OFF;
    float* a_sh    = sm + ASH_OFF;
    u64*   exp_pk  = (u64*)(sm + EXPPK_OFF);
    float* bias_sh = sm + BIAS_OFF;
    float* den_sh  = sm + DENP_OFF;

    const int t     = threadIdx.x;
    const int chunk = blockIdx.x;
    const int b     = blockIdx.y;
    const int lane  = t & 31;
    const int warp  = t >> 5;

    const uint32_t smem_base = smem_u32(sm);
    const uint32_t MB = smem_base + MBAR_OFF * 4u;
#define EXPFULL_MB(i)  (MB + (i) * 8u)
#define EXPEMPTY_MB(i) (MB + 32u + (i) * 8u)

    if (t == 0) {
#pragma unroll
        for (int i = 0; i < NEB; i++) { mbar_init(EXPFULL_MB(i), 128); mbar_init(EXPEMPTY_MB(i), 128); }
    }
    // stage W transposed [h][e] split in two 4-wide halves, + bias
    for (int i = t; i < EE * HH; i += 256) {
        int e = i / HH, h = i % HH;
        float v = W[i];
        if (e < 4) wlo[h * 4 + e]       = v;
        else       whi[h * 4 + (e - 4)] = v;
    }
    if (t < EE) bias_sh[t] = bias[t];

    const float* xbase = x + ((size_t)b * SS + (size_t)chunk * ROWS_PER_BLK) * HH;
    __syncthreads();

    if (t < 128) {
        // ======= A-group: warp-autonomous logits + softmax weights =======
        // warp = eh*2 + rp: e-half eh (4 heads), row-quad rp (rows 4rp..4rp+3)
        const int eh = warp >> 1;
        const int rp = warp & 1;
        const float* wbase = eh ? whi : wlo;
        float den_part = 0.f;

        for (int tile = 0; tile < NTILES; tile++) {
            const int stage = tile & (NEB - 1);
            const float* gxt = xbase + (size_t)tile * TS * HH + 4 * rp * HH;

            u64 acc2[2][4];
#pragma unroll
            for (int p = 0; p < 2; p++)
#pragma unroll
                for (int sl = 0; sl < 4; sl++) acc2[p][sl] = 0ull;

#pragma unroll
            for (int jj = 0; jj < 6; jj++) {
                int h0 = 4 * lane + 128 * jj;
                // 4 rows x 4 h via LDG.128 (coalesced, lead reader)
                float4 xr[4];
#pragma unroll
                for (int sl = 0; sl < 4; sl++)
                    xr[sl] = *(const float4*)(gxt + sl * HH + h0);
                float xa[4][4];
#pragma unroll
                for (int sl = 0; sl < 4; sl++) {
                    xa[sl][0] = xr[sl].x; xa[sl][1] = xr[sl].y;
                    xa[sl][2] = xr[sl].z; xa[sl][3] = xr[sl].w;
                }
#pragma unroll
                for (int hh = 0; hh < 4; hh++) {
                    ulonglong2 w2 = *(const ulonglong2*)&wbase[(h0 + hh) << 2];
#pragma unroll
                    for (int sl = 0; sl < 4; sl++) {
                        u64 xp = pack2(xa[sl][hh], xa[sl][hh]);
                        ffma2(acc2[0][sl], w2.x, xp);
                        ffma2(acc2[1][sl], w2.y, xp);
                    }
                }
            }

            float acc[16];
#pragma unroll
            for (int p = 0; p < 2; p++)
#pragma unroll
                for (int sl = 0; sl < 4; sl++)
                    unpack2(acc2[p][sl], acc[(2 * p) * 4 + sl], acc[(2 * p + 1) * 4 + sl]);

            red_round<8>(acc, lane);
            red_round<4>(acc, lane);
            red_round<2>(acc, lane);
            red_round<1>(acc, lane);
            acc[0] += __shfl_xor_sync(0xffffffffu, acc[0], 16);
            // lane<16 now holds full logit for m = lane

            mbar_wait(EXPEMPTY_MB(stage), ((tile / NEB) ^ 1) & 1);
            if (lane < 16) {
                int m  = lane;
                int e  = eh * 4 + (m >> 2);
                int sl = m & 3;
                int s_local = 4 * rp + sl;
                float a = acc[0] + bias_sh[e];
                a_sh[e * 128 + tile * TS + s_local] = a;
                float ev = __expf(a);
                den_part += ev;
                exp_pk[stage * 64 + s_local * 8 + e] = pack2(ev, ev);
            }
            mbar_arrive(EXPFULL_MB(stage));
        }
        if (lane < 16) den_sh[warp * 16 + lane] = den_part;
    } else {
        // ===== B-group: weighted accumulation, x from L2 (trailing reader) =====
        const int tb = t - 128;        // 0..127, owns h = 2*tb + 256k (+1)
        u64 accp[EE][3];
#pragma unroll
        for (int e = 0; e < EE; e++) { accp[e][0] = 0ull; accp[e][1] = 0ull; accp[e][2] = 0ull; }

        for (int tile = 0; tile < NTILES; tile++) {
            const int stage = tile & (NEB - 1);
            const u64* gxu = (const u64*)(xbase + (size_t)tile * TS * HH) + tb;

            // prefetch rows 0..2 BEFORE the exp wait (x is read-only)
            u64 xr[3][3];
#pragma unroll
            for (int ss = 0; ss < 3; ss++)
#pragma unroll
                for (int k = 0; k < 3; k++)
                    xr[ss][k] = ldg_cg_u64(gxu + ss * (HH / 2) + 128 * k);

            mbar_wait(EXPFULL_MB(stage), (tile / NEB) & 1);
            const ulonglong2* eb = (const ulonglong2*)(exp_pk + stage * 64);

#pragma unroll
            for (int s = 0; s < TS; s++) {
                ulonglong2 q0 = eb[s * 4 + 0];   // (e0,e0),(e1,e1)
                ulonglong2 q1 = eb[s * 4 + 1];
                ulonglong2 q2 = eb[s * 4 + 2];
                ulonglong2 q3 = eb[s * 4 + 3];
                int slot = s % 3;
                u64 x0 = xr[slot][0], x1 = xr[slot][1], x2 = xr[slot][2];
                ffma2(accp[0][0], q0.x, x0); ffma2(accp[0][1], q0.x, x1); ffma2(accp[0][2], q0.x, x2);
                ffma2(accp[1][0], q0.y, x0); ffma2(accp[1][1], q0.y, x1); ffma2(accp[1][2], q0.y, x2);
                ffma2(accp[2][0], q1.x, x0); ffma2(accp[2][1], q1.x, x1); ffma2(accp[2][2], q1.x, x2);
                ffma2(accp[3][0], q1.y, x0); ffma2(accp[3][1], q1.y, x1); ffma2(accp[3][2], q1.y, x2);
                ffma2(accp[4][0], q2.x, x0); ffma2(accp[4][1], q2.x, x1); ffma2(accp[4][2], q2.x, x2);
                ffma2(accp[5][0], q2.y, x0); ffma2(accp[5][1], q2.y, x1); ffma2(accp[5][2], q2.y, x2);
                ffma2(accp[6][0], q3.x, x0); ffma2(accp[6][1], q3.x, x1); ffma2(accp[6][2], q3.x, x2);
                ffma2(accp[7][0], q3.y, x0); ffma2(accp[7][1], q3.y, x1); ffma2(accp[7][2], q3.y, x2);
                if (s + 3 < TS) {
#pragma unroll
                    for (int k = 0; k < 3; k++)
                        xr[slot][k] = ldg_cg_u64(gxu + (s + 3) * (HH / 2) + 128 * k);
                }
            }
            mbar_arrive(EXPEMPTY_MB(stage));
        }

        // write per-block numerator partials: h = 2*tb + 256k
        int blk = b * CHUNKS + chunk;
#pragma unroll
        for (int e = 0; e < EE; e++)
#pragma unroll
            for (int k = 0; k < 3; k++) {
                float lo, hi;
                unpack2(accp[e][k], lo, hi);
                float2 v = make_float2(lo, hi);
                *(float2*)&g_num[((size_t)blk * EE + e) * HH + 2 * tb + 256 * k] = v;
            }
    }

    __syncthreads();

    // atten logits: coalesced write from a_sh
    for (int f = t; f < EE * ROWS_PER_BLK; f += 256) {
        int e = f >> 7, i = f & 127;
        attn_out[((size_t)b * EE + e) * SS + chunk * ROWS_PER_BLK + i] = a_sh[f];
    }
    // denominator: per e, 8 partials at den_sh[((e>>2)*2+rp)*16 + (e&3)*4 + sl]
    if (t < EE) {
        float d = 0.f;
#pragma unroll
        for (int rp = 0; rp < 2; rp++)
#pragma unroll
            for (int sl = 0; sl < 4; sl++)
                d += den_sh[(((t >> 2) * 2) + rp) * 16 + (t & 3) * 4 + sl];
        g_den[(b * CHUNKS + chunk) * EE + t] = d;
    }
}

__global__ __launch_bounds__(128)
void fused_attn_pass2(float* __restrict__ out)
{
    __shared__ float inv_sh;
    const int e = blockIdx.y, b = blockIdx.z;
    const int h = blockIdx.x * 128 + threadIdx.x;

    if (threadIdx.x == 0) {
        float den = 0.f;
#pragma unroll
        for (int c = 0; c < CHUNKS; c++) den += g_den[(b * CHUNKS + c) * EE + e];
        inv_sh = 1.0f / den;
    }
    __syncthreads();

    const float* base = g_num + ((size_t)(b * CHUNKS) * EE + e) * HH + h;
    float s = 0.f;
#pragma unroll
    for (int c = 0; c < CHUNKS; c++)
        s += base[(size_t)c * EE * HH];
    out[((size_t)b * EE + e) * HH + h] = s * inv_sh;
}

extern "C" void kernel_launch(void* const* d_in, const int* in_sizes, int n_in,
                              void* d_out, int out_size)
{
    const float* x    = (const float*)d_in[0];
    const float* W    = (const float*)d_in[1];
    const float* bias = (const float*)d_in[2];

    float* out_f = (float*)d_out;
    float* out_ptr;
    float* attn_ptr;

    const int OUT_N  = BB * EE * HH;          // 98304
    const int ATTN_N = BB * EE * SS;          // 524288

    if (out_size >= OUT_N + ATTN_N) {
        out_ptr  = out_f;
        attn_ptr = out_f + OUT_N;
    } else if (out_size == ATTN_N) {
        out_ptr  = nullptr;
        attn_ptr = out_f;
    } else {
        out_ptr  = out_f;
        float* dev_scratch;
        cudaGetSymbolAddress((void**)&dev_scratch, g_attn_scratch);
        attn_ptr = dev_scratch;
    }
    if (!out_ptr) {
        float* dev_scratch;
        cudaGetSymbolAddress((void**)&dev_scratch, g_attn_scratch);
        out_ptr = dev_scratch;
    }

    size_t smem_bytes = (size_t)SMEM_FLOATS * sizeof(float);
    fused_attn_pass1<<<dim3(CHUNKS, BB), 256, smem_bytes>>>(x, W, bias, attn_ptr);
    fused_attn_pass2<<<dim3(6, EE, BB), 128>>>(out_ptr);
}

// round 15
// speedup vs baseline: 2.9574x; 2.9574x over previous
#include <cuda_runtime.h>
#include <math.h>
#include <stdint.h>

#define BB 16
#define SS 4096
#define HH 768
#define EE 8
#define CHUNKS 16
#define ROWS_PER_BLK 256
#define TS 8
#define NTILES 32          // ROWS_PER_BLK/TS
#define NBUF 3
#define NEB 4
#define TILE_BYTES (TS * HH * 4)   // 24576
#define XS_STRIDE 6144             // floats per x buffer

// smem layout in floats
#define XS_OFF    0                // 3 x 6144 = 18432
#define WLO_OFF   18432            // [768][4] = 3072  (e0..e3)
#define WHI_OFF   21504            // [768][4] = 3072  (e4..e7)
#define ASH_OFF   24576            // [8][256] = 2048
#define EXPPK_OFF 26624            // NEB x 64 u64 = 512 floats (8B aligned)
#define RED_OFF   27136            // [4 warps][32] = 128
#define BIAS_OFF  27264            // [8]
#define DENP_OFF  27272            // [64]
#define MBAR_OFF  27336            // 14 barriers x 8B = 28 floats (8B aligned)
#define SMEM_FLOATS 27368          // 109472 bytes -> 2 CTAs/SM (~213.8KB)

__device__ float g_num[(size_t)BB * CHUNKS * EE * HH];   // 6.3 MB
__device__ float g_den[BB * CHUNKS * EE];
__device__ float g_attn_scratch[(size_t)BB * EE * SS];

typedef unsigned long long u64;

__device__ __forceinline__ u64 pack2(float lo, float hi) {
    u64 r; asm("mov.b64 %0, {%1, %2};" : "=l"(r) : "f"(lo), "f"(hi)); return r;
}
__device__ __forceinline__ void unpack2(u64 v, float& lo, float& hi) {
    asm("mov.b64 {%0, %1}, %2;" : "=f"(lo), "=f"(hi) : "l"(v));
}
__device__ __forceinline__ void ffma2(u64& d, u64 a, u64 b) {
    asm("fma.rn.f32x2 %0, %1, %2, %3;" : "=l"(d) : "l"(a), "l"(b), "l"(d));
}
__device__ __forceinline__ void mbar_init(uint32_t mbar, uint32_t cnt) {
    asm volatile("mbarrier.init.shared.b64 [%0], %1;" :: "r"(mbar), "r"(cnt) : "memory");
}
__device__ __forceinline__ void mbar_expect_tx(uint32_t mbar, uint32_t bytes) {
    asm volatile("mbarrier.arrive.expect_tx.shared.b64 _, [%0], %1;"
                 :: "r"(mbar), "r"(bytes) : "memory");
}
__device__ __forceinline__ void mbar_arrive(uint32_t mbar) {
    asm volatile("mbarrier.arrive.shared.b64 _, [%0];" :: "r"(mbar) : "memory");
}
__device__ __forceinline__ void mbar_wait(uint32_t mbar, uint32_t parity) {
    asm volatile(
        "{\n\t.reg .pred P1;\n\t"
        "WAIT_%=:\n\t"
        "mbarrier.try_wait.parity.acquire.cta.shared::cta.b64 P1, [%0], %1, 0x989680;\n\t"
        "@P1 bra.uni DONE_%=;\n\t"
        "bra.uni WAIT_%=;\n\t"
        "DONE_%=:\n\t}"
        :: "r"(mbar), "r"(parity) : "memory");
}
__device__ __forceinline__ void bulk_g2s(uint32_t dst, const void* src,
                                         uint32_t bytes, uint32_t mbar) {
    asm volatile(
        "cp.async.bulk.shared::cluster.global.mbarrier::complete_tx::bytes "
        "[%0], [%1], %2, [%3];"
        :: "r"(dst), "l"(src), "r"(bytes), "r"(mbar) : "memory");
}
__device__ __forceinline__ uint32_t smem_u32(const void* p) {
    uint32_t a;
    asm("{ .reg .u64 t; cvta.to.shared.u64 t, %1; cvt.u32.u64 %0, t; }" : "=r"(a) : "l"(p));
    return a;
}

template <int HALF>
__device__ __forceinline__ void red_round(float* v, int lane) {
    bool hi = (lane & HALF) != 0;
#pragma unroll
    for (int m = 0; m < HALF; m++) {
        float mine  = hi ? v[m + HALF] : v[m];
        float yours = hi ? v[m]        : v[m + HALF];
        v[m] = mine + __shfl_xor_sync(0xffffffffu, yours, HALF);
    }
}

__global__ __launch_bounds__(256, 2)
void fused_attn_pass1(const float* __restrict__ x,
                      const float* __restrict__ W,
                      const float* __restrict__ bias,
                      float* __restrict__ attn_out)
{
    extern __shared__ float sm[];
    float* wlo     = sm + WLO_OFF;
    float* whi     = sm + WHI_OFF;
    float* a_sh    = sm + ASH_OFF;
    u64*   exp_pk  = (u64*)(sm + EXPPK_OFF);
    float* red_sh  = sm + RED_OFF;
    float* bias_sh = sm + BIAS_OFF;
    float* den_sh  = sm + DENP_OFF;

    const int t     = threadIdx.x;
    const int chunk = blockIdx.x;   // 0..15
    const int b     = blockIdx.y;   // 0..15
    const int lane  = t & 31;
    const int warp  = t >> 5;

    const uint32_t smem_base = smem_u32(sm);
    const uint32_t MB = smem_base + MBAR_OFF * 4u;
#define FULL_MB(i)     (MB + (i) * 8u)
#define EMPTY_MB(i)    (MB + 24u + (i) * 8u)
#define EXPFULL_MB(i)  (MB + 48u + (i) * 8u)
#define EXPEMPTY_MB(i) (MB + 80u + (i) * 8u)

    if (t == 0) {
#pragma unroll
        for (int i = 0; i < NBUF; i++) { mbar_init(FULL_MB(i), 1); mbar_init(EMPTY_MB(i), 256); }
#pragma unroll
        for (int i = 0; i < NEB; i++)  { mbar_init(EXPFULL_MB(i), 64); mbar_init(EXPEMPTY_MB(i), 128); }
    }
    // stage W transposed [h][e] split in two 4-wide halves, + bias
    for (int i = t; i < EE * HH; i += 256) {
        int e = i / HH, h = i % HH;
        float v = W[i];
        if (e < 4) wlo[h * 4 + e]       = v;
        else       whi[h * 4 + (e - 4)] = v;
    }
    if (t < EE) bias_sh[t] = bias[t];

    const float* xbase = x + ((size_t)b * SS + (size_t)chunk * ROWS_PER_BLK) * HH;
    __syncthreads();

    if (t == 128) {   // producer prologue: fill the 3-deep ring
#pragma unroll
        for (int k = 0; k < NBUF; k++) {
            mbar_expect_tx(FULL_MB(k), TILE_BYTES);
            bulk_g2s(smem_base + (XS_OFF + k * XS_STRIDE) * 4u,
                     xbase + (size_t)k * TS * HH, TILE_BYTES, FULL_MB(k));
        }
    }

    if (t < 128) {
        // ================= A-group: logits + softmax weights =================
        const int hg = t & 63;         // h-slice (64 wide, warp pair)
        const int sg = t >> 6;         // s-group: 4 rows each
        float den_part = 0.f;

        for (int tile = 0; tile < NTILES; tile++) {
            const int buf   = tile % NBUF;
            const int stage = tile & (NEB - 1);
            mbar_wait(FULL_MB(buf), (tile / NBUF) & 1);
            const float* xs = sm + XS_OFF + buf * XS_STRIDE;

            u64 acc2[4][4];
#pragma unroll
            for (int p = 0; p < 4; p++)
#pragma unroll
                for (int sl = 0; sl < 4; sl++) acc2[p][sl] = 0ull;

#pragma unroll
            for (int j = 0; j < 12; j++) {
                int h = hg + 64 * j;
                ulonglong2 wl = *(const ulonglong2*)&wlo[h << 2];
                ulonglong2 wh = *(const ulonglong2*)&whi[h << 2];
                u64 xp[4];
#pragma unroll
                for (int sl = 0; sl < 4; sl++) {
                    float xv = xs[(4 * sg + sl) * HH + h];
                    xp[sl] = pack2(xv, xv);
                }
#pragma unroll
                for (int sl = 0; sl < 4; sl++) {
                    ffma2(acc2[0][sl], wl.x, xp[sl]);
                    ffma2(acc2[1][sl], wl.y, xp[sl]);
                    ffma2(acc2[2][sl], wh.x, xp[sl]);
                    ffma2(acc2[3][sl], wh.y, xp[sl]);
                }
            }
            mbar_arrive(EMPTY_MB(buf));    // done reading xs

            float acc[32];
#pragma unroll
            for (int p = 0; p < 4; p++)
#pragma unroll
                for (int sl = 0; sl < 4; sl++)
                    unpack2(acc2[p][sl], acc[(2 * p) * 4 + sl], acc[(2 * p + 1) * 4 + sl]);

            red_round<16>(acc, lane);
            red_round<8>(acc, lane);
            red_round<4>(acc, lane);
            red_round<2>(acc, lane);
            red_round<1>(acc, lane);
            red_sh[warp * 32 + lane] = acc[0];   // warp-partial for m=lane
            asm volatile("bar.sync 1, 128;" ::: "memory");

            if (t < 64) {
                mbar_wait(EXPEMPTY_MB(stage), ((tile / NEB) ^ 1) & 1);
                int sgf = t >> 5;
                int m   = t & 31;
                int e   = m >> 2;
                int sl  = m & 3;
                float a = red_sh[(2 * sgf) * 32 + m] + red_sh[(2 * sgf + 1) * 32 + m]
                          + bias_sh[e];
                int s_local = 4 * sgf + sl;
                a_sh[e * ROWS_PER_BLK + tile * TS + s_local] = a;
                float ev = __expf(a);
                den_part += ev;
                exp_pk[stage * 64 + s_local * 8 + e] = pack2(ev, ev);
                mbar_arrive(EXPFULL_MB(stage));
            }
            asm volatile("bar.sync 1, 128;" ::: "memory");   // red_sh reuse next tile
        }
        if (t < 64) den_sh[t] = den_part;
    } else {
        // ================= B-group: weighted accumulation =================
        const int tb = t - 128;        // 0..127, owns h = 2*tb + 256k (+1)
        u64 accp[EE][3];
#pragma unroll
        for (int e = 0; e < EE; e++) { accp[e][0] = 0ull; accp[e][1] = 0ull; accp[e][2] = 0ull; }

        for (int tile = 0; tile < NTILES; tile++) {
            const int buf   = tile % NBUF;
            const int stage = tile & (NEB - 1);
            mbar_wait(EXPFULL_MB(stage), (tile / NEB) & 1);
            mbar_wait(FULL_MB(buf), (tile / NBUF) & 1);     // usually already passed
            const float* xs = sm + XS_OFF + buf * XS_STRIDE;
            const ulonglong2* eb = (const ulonglong2*)(exp_pk + stage * 64);

#pragma unroll
            for (int s = 0; s < TS; s++) {
                ulonglong2 q0 = eb[s * 4 + 0];   // (e0,e0),(e1,e1)
                ulonglong2 q1 = eb[s * 4 + 1];
                ulonglong2 q2 = eb[s * 4 + 2];
                ulonglong2 q3 = eb[s * 4 + 3];
                u64 x0 = *(const u64*)&xs[s * HH + 2 * tb];
                u64 x1 = *(const u64*)&xs[s * HH + 2 * tb + 256];
                u64 x2 = *(const u64*)&xs[s * HH + 2 * tb + 512];
                ffma2(accp[0][0], q0.x, x0); ffma2(accp[0][1], q0.x, x1); ffma2(accp[0][2], q0.x, x2);
                ffma2(accp[1][0], q0.y, x0); ffma2(accp[1][1], q0.y, x1); ffma2(accp[1][2], q0.y, x2);
                ffma2(accp[2][0], q1.x, x0); ffma2(accp[2][1], q1.x, x1); ffma2(accp[2][2], q1.x, x2);
                ffma2(accp[3][0], q1.y, x0); ffma2(accp[3][1], q1.y, x1); ffma2(accp[3][2], q1.y, x2);
                ffma2(accp[4][0], q2.x, x0); ffma2(accp[4][1], q2.x, x1); ffma2(accp[4][2], q2.x, x2);
                ffma2(accp[5][0], q2.y, x0); ffma2(accp[5][1], q2.y, x1); ffma2(accp[5][2], q2.y, x2);
                ffma2(accp[6][0], q3.x, x0); ffma2(accp[6][1], q3.x, x1); ffma2(accp[6][2], q3.x, x2);
                ffma2(accp[7][0], q3.y, x0); ffma2(accp[7][1], q3.y, x1); ffma2(accp[7][2], q3.y, x2);
            }
            mbar_arrive(EMPTY_MB(buf));
            mbar_arrive(EXPEMPTY_MB(stage));

            // producer: refill this buffer with tile+NBUF once fully released
            if (t == 128 && tile + NBUF < NTILES) {
                mbar_wait(EMPTY_MB(buf), (tile / NBUF) & 1);
                mbar_expect_tx(FULL_MB(buf), TILE_BYTES);
                bulk_g2s(smem_base + (XS_OFF + buf * XS_STRIDE) * 4u,
                         xbase + (size_t)(tile + NBUF) * TS * HH, TILE_BYTES, FULL_MB(buf));
            }
        }

        // write per-block numerator partials: h = 2*tb + 256k
        int blk = b * CHUNKS + chunk;
#pragma unroll
        for (int e = 0; e < EE; e++)
#pragma unroll
            for (int k = 0; k < 3; k++) {
                float lo, hi;
                unpack2(accp[e][k], lo, hi);
                float2 v = make_float2(lo, hi);
                *(float2*)&g_num[((size_t)blk * EE + e) * HH + 2 * tb + 256 * k] = v;
            }
    }

    __syncthreads();

    // atten logits: coalesced write from a_sh
    for (int f = t; f < EE * ROWS_PER_BLK; f += 256) {
        int e = f >> 8, i = f & 255;
        attn_out[((size_t)b * EE + e) * SS + chunk * ROWS_PER_BLK + i] = a_sh[f];
    }
    // denominator: 8 partials per e in den_sh
    if (t < EE) {
        float d = 0.f;
#pragma unroll
        for (int sgf = 0; sgf < 2; sgf++)
#pragma unroll
            for (int sl = 0; sl < 4; sl++)
                d += den_sh[sgf * 32 + t * 4 + sl];
        g_den[(b * CHUNKS + chunk) * EE + t] = d;
    }
}

__global__ __launch_bounds__(192)
void fused_attn_pass2(float* __restrict__ out)
{
    __shared__ float inv_sh;
    const int e = blockIdx.y, b = blockIdx.z;
    const int h4 = threadIdx.x;        // 0..191 -> h = 4*h4

    if (threadIdx.x == 0) {
        float den = 0.f;
#pragma unroll
        for (int c = 0; c < CHUNKS; c++) den += g_den[(b * CHUNKS + c) * EE + e];
        inv_sh = 1.0f / den;
    }
    __syncthreads();

    const float4* base = (const float4*)(g_num + ((size_t)(b * CHUNKS) * EE + e) * HH) + h4;
    float4 s = make_float4(0.f, 0.f, 0.f, 0.f);
#pragma unroll
    for (int c = 0; c < CHUNKS; c++) {
        float4 v = base[(size_t)c * EE * HH / 4];
        s.x += v.x; s.y += v.y; s.z += v.z; s.w += v.w;
    }
    float inv = inv_sh;
    s.x *= inv; s.y *= inv; s.z *= inv; s.w *= inv;
    ((float4*)(out + ((size_t)b * EE + e) * HH))[h4] = s;
}

extern "C" void kernel_launch(void* const* d_in, const int* in_sizes, int n_in,
                              void* d_out, int out_size)
{
    const float* x    = (const float*)d_in[0];
    const float* W    = (const float*)d_in[1];
    const float* bias = (const float*)d_in[2];

    float* out_f = (float*)d_out;
    float* out_ptr;
    float* attn_ptr;

    const int OUT_N  = BB * EE * HH;          // 98304
    const int ATTN_N = BB * EE * SS;          // 524288

    if (out_size >= OUT_N + ATTN_N) {
        out_ptr  = out_f;
        attn_ptr = out_f + OUT_N;
    } else if (out_size == ATTN_N) {
        out_ptr  = nullptr;
        attn_ptr = out_f;
    } else {
        out_ptr  = out_f;
        float* dev_scratch;
        cudaGetSymbolAddress((void**)&dev_scratch, g_attn_scratch);
        attn_ptr = dev_scratch;
    }
    if (!out_ptr) {
        float* dev_scratch;
        cudaGetSymbolAddress((void**)&dev_scratch, g_attn_scratch);
        out_ptr = dev_scratch;
    }

    size_t smem_bytes = (size_t)SMEM_FLOATS * sizeof(float);
    cudaFuncSetAttribute(fused_attn_pass1,
                         cudaFuncAttributeMaxDynamicSharedMemorySize, (int)smem_bytes);

    fused_attn_pass1<<<dim3(CHUNKS, BB), 256, smem_bytes>>>(x, W, bias, attn_ptr);
    fused_attn_pass2<<<dim3(1, EE, BB), 192>>>(out_ptr);
}